// round 2
// baseline (speedup 1.0000x reference)
#include <cuda_runtime.h>
#include <cstdint>
#include <cstddef>

#define L_  6
#define B_  8
#define Q_  2048
#define C_  256
#define P_  128
#define FF_ 1024
#define R_  (B_*Q_)   // 16384 rows

static const size_t INTERM_OFF = 0;
static const size_t REFS_OFF   = (size_t)L_*R_*C_;                 // 25,165,824
static const size_t LOGITS_OFF = REFS_OFF + (size_t)(L_+1)*R_*3;   // 25,509,888

// ---------------- device state (no allocations allowed) ----------------
__device__ float g_query [R_*C_];
__device__ float g_qpos  [R_*C_];
__device__ float g_H     [R_*FF_];
__device__ float g_logits[R_*P_];
__device__ float g_S     [R_*P_];
__device__ float g_probs [R_*P_];
__device__ float g_lnpos [R_*C_];
__device__ float g_t1    [R_*C_];
__device__ float g_t2    [R_*C_];
__device__ float g_ref   [R_*3];

// ---------------- reductions ----------------
__device__ __forceinline__ float warp_sum(float v){
#pragma unroll
    for (int o = 16; o; o >>= 1) v += __shfl_xor_sync(0xffffffffu, v, o);
    return v;
}
__device__ __forceinline__ float warp_max(float v){
#pragma unroll
    for (int o = 16; o; o >>= 1) v = fmaxf(v, __shfl_xor_sync(0xffffffffu, v, o));
    return v;
}

// ---------------- SGEMM: C = epi(A (+A2) @ B + bias [+ Cres]) ----------------
// BM=BN=128, BK=8, 256 threads, 8x8 per thread. M,N,K all multiples of tile dims here.
template<bool ADD_A2, int EPI>   // EPI: 0=relu(.+b), 1=Cres+.+b, 2=.+b
__global__ __launch_bounds__(256)
void sgemm(int M, int N, int K,
           const float* __restrict__ A, const float* __restrict__ A2,
           const float* __restrict__ Bm, const float* __restrict__ bias,
           const float* __restrict__ Cres, float* __restrict__ Cout)
{
    const int BM = 128, BN = 128, BK = 8, TM = 8, TN = 8;
    __shared__ float As[BK][BM];
    __shared__ float Bs[BK][BN];
    int tid = threadIdx.x;
    int bm = blockIdx.y, bn = blockIdx.x;
    int tr = tid >> 4, tc = tid & 15;

    int aRow = tid >> 1, aCol = (tid & 1) * 4;
    int bRow = tid >> 5, bCol = (tid & 31) * 4;

    const float* Ap  = A  + (size_t)(bm*BM + aRow)*K + aCol;
    const float* A2p = ADD_A2 ? (A2 + (size_t)(bm*BM + aRow)*K + aCol) : nullptr;
    const float* Bp  = Bm + (size_t)bRow*N + bn*BN + bCol;

    float acc[TM][TN] = {};

    for (int k0 = 0; k0 < K; k0 += BK) {
        float4 av = *(const float4*)Ap;
        if (ADD_A2) {
            float4 a2 = *(const float4*)A2p;
            av.x += a2.x; av.y += a2.y; av.z += a2.z; av.w += a2.w;
            A2p += BK;
        }
        As[aCol+0][aRow] = av.x;
        As[aCol+1][aRow] = av.y;
        As[aCol+2][aRow] = av.z;
        As[aCol+3][aRow] = av.w;
        *(float4*)&Bs[bRow][bCol] = *(const float4*)Bp;
        __syncthreads();
        Ap += BK;
        Bp += (size_t)BK * N;

#pragma unroll
        for (int kk = 0; kk < BK; kk++) {
            float ar[TM], br[TN];
#pragma unroll
            for (int i = 0; i < TM; i++) ar[i] = As[kk][tr*TM + i];
#pragma unroll
            for (int j = 0; j < TN; j++) br[j] = Bs[kk][tc*TN + j];
#pragma unroll
            for (int i = 0; i < TM; i++)
#pragma unroll
                for (int j = 0; j < TN; j++)
                    acc[i][j] += ar[i] * br[j];
        }
        __syncthreads();
    }

#pragma unroll
    for (int i = 0; i < TM; i++) {
        int row = bm*BM + tr*TM + i;
#pragma unroll
        for (int j = 0; j < TN; j += 4) {
            int col = bn*BN + tc*TN + j;
            float4 o;
            float* po = &o.x;
#pragma unroll
            for (int jj = 0; jj < 4; jj++) {
                float v = acc[i][j+jj] + bias[col+jj];
                if (EPI == 0)      v = fmaxf(v, 0.f);
                else if (EPI == 1) v += Cres[(size_t)row*N + col + jj];
                po[jj] = v;
            }
            *(float4*)&Cout[(size_t)row*N + col] = o;
        }
    }
}

// ---------------- logits init: log(max(p,1e-8)) ----------------
__global__ void logits_init(const float* __restrict__ p, float* __restrict__ lg)
{
    int i = blockIdx.x * blockDim.x + threadIdx.x;
    if (i < R_*P_) lg[i] = logf(fmaxf(p[i], 1e-8f));
}

// ---------------- plain row LN (256 cols, 128 threads) ----------------
__global__ void ln_rows(const float* __restrict__ in, float* __restrict__ out)
{
    int row = blockIdx.x, t = threadIdx.x;
    int w = t >> 5, lane = t & 31;
    __shared__ float sr[8];
    float x0 = in[(size_t)row*C_ + t];
    float x1 = in[(size_t)row*C_ + 128 + t];
    float s1 = warp_sum(x0 + x1);
    float s2 = warp_sum(x0*x0 + x1*x1);
    if (lane == 0) { sr[w] = s1; sr[4+w] = s2; }
    __syncthreads();
    float m  = (sr[0]+sr[1]+sr[2]+sr[3]) * (1.f/256.f);
    float vv = (sr[4]+sr[5]+sr[6]+sr[7]) * (1.f/256.f) - m*m;
    float r  = rsqrtf(vv + 1e-5f);
    out[(size_t)row*C_ + t]       = (x0 - m) * r;
    out[(size_t)row*C_ + 128 + t] = (x1 - m) * r;
}

// ---------------- per-row fused: LN->interm, logits+softmax, ref einsum ----------------
__global__ void row_kernel(int layer,
                           const float* __restrict__ query,
                           const float* __restrict__ S,
                           const float* __restrict__ coords,
                           const int* __restrict__ mask,
                           const float* __restrict__ pn_scale,
                           const float* __restrict__ pn_bias,
                           float* __restrict__ logits_st,
                           float* __restrict__ probs,
                           float* __restrict__ ref_st,
                           float* __restrict__ out)
{
    int row = blockIdx.x, t = threadIdx.x;
    int w = t >> 5, lane = t & 31;
    __shared__ float sr[12];

    // --- layernorm of query -> interm output ---
    float x0 = query[(size_t)row*C_ + t];
    float x1 = query[(size_t)row*C_ + 128 + t];
    float s1 = warp_sum(x0 + x1);
    float s2 = warp_sum(x0*x0 + x1*x1);
    if (lane == 0) { sr[w] = s1; sr[4+w] = s2; }
    __syncthreads();
    float m    = (sr[0]+sr[1]+sr[2]+sr[3]) * (1.f/256.f);
    float var  = (sr[4]+sr[5]+sr[6]+sr[7]) * (1.f/256.f) - m*m;
    float rstd = rsqrtf(var + 1e-5f);
    size_t ib = INTERM_OFF + (size_t)layer*R_*C_ + (size_t)row*C_;
    out[ib + t]       = (x0 - m)*rstd*pn_scale[t]       + pn_bias[t];
    out[ib + 128 + t] = (x1 - m)*rstd*pn_scale[128 + t] + pn_bias[128 + t];

    // --- masked logits residual update ---
    float mf = mask[row] ? 1.f : 0.f;
    size_t li = (size_t)row*P_ + t;
    float lg = logits_st[li] + S[li] * mf;
    logits_st[li] = lg;
    out[LOGITS_OFF + (size_t)layer*R_*P_ + li] = lg;

    // --- softmax over 128 ---
    float mx = warp_max(lg);
    __syncthreads();
    if (lane == 0) sr[w] = mx;
    __syncthreads();
    mx = fmaxf(fmaxf(sr[0], sr[1]), fmaxf(sr[2], sr[3]));
    float e = __expf(lg - mx);
    float se = warp_sum(e);
    __syncthreads();
    if (lane == 0) sr[w] = se;
    __syncthreads();
    se = sr[0]+sr[1]+sr[2]+sr[3];
    float p = e / se;
    probs[li] = p;

    // --- dyn_ref = probs @ coords[row] (128x3) ---
    const float* cr = coords + (size_t)row*P_*3 + (size_t)t*3;
    float r0 = warp_sum(p * cr[0]);
    float r1 = warp_sum(p * cr[1]);
    float r2 = warp_sum(p * cr[2]);
    __syncthreads();
    if (lane == 0) { sr[w] = r0; sr[4+w] = r1; sr[8+w] = r2; }
    __syncthreads();
    if (t == 0) {
        float d0 = sr[0]+sr[1]+sr[2]+sr[3];
        float d1 = sr[4]+sr[5]+sr[6]+sr[7];
        float d2 = sr[8]+sr[9]+sr[10]+sr[11];
        float o0, o1, o2;
        if (mf > 0.f) { o0 = d0; o1 = d1; o2 = d2; }
        else { o0 = ref_st[row*3]; o1 = ref_st[row*3+1]; o2 = ref_st[row*3+2]; }
        ref_st[row*3] = o0; ref_st[row*3+1] = o1; ref_st[row*3+2] = o2;
        size_t rb = REFS_OFF + (size_t)(layer+1)*R_*3 + (size_t)row*3;
        out[rb] = o0; out[rb+1] = o1; out[rb+2] = o2;
    }
}

// ---------------- masked query_pos update ----------------
__global__ void pos_update(const float* __restrict__ t1, const float* __restrict__ t2,
                           const float* __restrict__ lnp, const int* __restrict__ mask,
                           float* __restrict__ qpos)
{
    int idx = blockIdx.x * blockDim.x + threadIdx.x;
    if (idx >= R_*C_) return;
    int row = idx >> 8;
    if (mask[row]) qpos[idx] = lnp[idx] * t1[idx] + t2[idx];
}

// ---------------- host ----------------
extern "C" void kernel_launch(void* const* d_in, const int* in_sizes, int n_in,
                              void* d_out, int out_size)
{
    const float*   query      = (const float*)d_in[0];
    const float*   query_pos  = (const float*)d_in[1];
    const float*   refpts     = (const float*)d_in[2];
    const float*   coords     = (const float*)d_in[3];
    const float*   dprobs     = (const float*)d_in[4];
    const int*     mask       = (const int*)d_in[5];
    const float*   layer_w1   = (const float*)d_in[6];
    const float*   layer_b1   = (const float*)d_in[7];
    const float*   layer_w2   = (const float*)d_in[8];
    const float*   layer_b2   = (const float*)d_in[9];
    const float*   prob_w     = (const float*)d_in[10];
    const float*   prob_b     = (const float*)d_in[11];
    const float*   pos_w      = (const float*)d_in[12];
    const float*   pos_b      = (const float*)d_in[13];
    const float*   g_w        = (const float*)d_in[14];
    const float*   g_b        = (const float*)d_in[15];
    const float*   be_w       = (const float*)d_in[16];
    const float*   be_b       = (const float*)d_in[17];
    const float*   pn_scale   = (const float*)d_in[18];
    const float*   pn_bias    = (const float*)d_in[19];
    float* out = (float*)d_out;

    float *q, *qp, *H, *lg, *S, *pb, *lnp, *t1, *t2, *ref;
    cudaGetSymbolAddress((void**)&q,   g_query);
    cudaGetSymbolAddress((void**)&qp,  g_qpos);
    cudaGetSymbolAddress((void**)&H,   g_H);
    cudaGetSymbolAddress((void**)&lg,  g_logits);
    cudaGetSymbolAddress((void**)&S,   g_S);
    cudaGetSymbolAddress((void**)&pb,  g_probs);
    cudaGetSymbolAddress((void**)&lnp, g_lnpos);
    cudaGetSymbolAddress((void**)&t1,  g_t1);
    cudaGetSymbolAddress((void**)&t2,  g_t2);
    cudaGetSymbolAddress((void**)&ref, g_ref);

    // init state
    cudaMemcpyAsync(q,   query,     (size_t)R_*C_*4, cudaMemcpyDeviceToDevice);
    cudaMemcpyAsync(qp,  query_pos, (size_t)R_*C_*4, cudaMemcpyDeviceToDevice);
    cudaMemcpyAsync(ref, refpts,    (size_t)R_*3*4,  cudaMemcpyDeviceToDevice);
    cudaMemcpyAsync(out + REFS_OFF, refpts, (size_t)R_*3*4, cudaMemcpyDeviceToDevice);

    logits_init<<<(R_*P_ + 255)/256, 256>>>(dprobs, lg);

    // pos_base = coords.reshape(R,384) @ pos_w + pos_b ; then LN -> g_lnpos
    sgemm<false,2><<<dim3(C_/128, R_/128), 256>>>(R_, C_, P_*3, coords, nullptr,
                                                  pos_w, pos_b, nullptr, t1);
    ln_rows<<<R_, 128>>>(t1, lnp);

    for (int i = 0; i < L_; i++) {
        // H = relu((q+qp) @ W1 + b1)
        sgemm<true,0><<<dim3(FF_/128, R_/128), 256>>>(R_, FF_, C_,
            q, qp, layer_w1 + (size_t)i*C_*FF_, layer_b1 + (size_t)i*FF_, nullptr, H);
        // q = q + H @ W2 + b2
        sgemm<false,1><<<dim3(C_/128, R_/128), 256>>>(R_, C_, FF_,
            H, nullptr, layer_w2 + (size_t)i*FF_*C_, layer_b2 + (size_t)i*C_, q, q);
        // S = q @ prob_w + prob_b
        sgemm<false,2><<<dim3(P_/128, R_/128), 256>>>(R_, P_, C_,
            q, nullptr, prob_w + (size_t)i*C_*P_, prob_b + (size_t)i*P_, nullptr, S);
        // per-row fused ops
        row_kernel<<<R_, 128>>>(i, q, S, coords, mask, pn_scale, pn_bias,
                                lg, pb, ref, out);
        // t1 = probs @ g_w + g_b ; t2 = probs @ be_w + be_b
        sgemm<false,2><<<dim3(C_/128, R_/128), 256>>>(R_, C_, P_,
            pb, nullptr, g_w, g_b, nullptr, t1);
        sgemm<false,2><<<dim3(C_/128, R_/128), 256>>>(R_, C_, P_,
            pb, nullptr, be_w, be_b, nullptr, t2);
        // qpos = mask ? lnpos * t1 + t2 : qpos
        pos_update<<<(R_*C_ + 255)/256, 256>>>(t1, t2, lnp, mask, qp);
    }
    (void)in_sizes; (void)n_in; (void)out_size;
}

// round 3
// speedup vs baseline: 1.8041x; 1.8041x over previous
#include <cuda_runtime.h>
#include <mma.h>
#include <cstdint>
#include <cstddef>

using namespace nvcuda;

#define L_  6
#define B_  8
#define Q_  2048
#define C_  256
#define P_  128
#define FF_ 1024
#define R_  (B_*Q_)   // 16384 rows

static const size_t INTERM_OFF = 0;
static const size_t REFS_OFF   = (size_t)L_*R_*C_;                 // 25,165,824
static const size_t LOGITS_OFF = REFS_OFF + (size_t)(L_+1)*R_*3;   // 25,509,888

// ---------------- device state (no allocations allowed) ----------------
__device__ float g_query [R_*C_];
__device__ float g_qpos  [R_*C_];
__device__ float g_H     [R_*FF_];
__device__ float g_logits[R_*P_];
__device__ float g_S     [R_*P_];
__device__ float g_probs [R_*P_];
__device__ float g_lnpos [R_*C_];
__device__ float g_t1    [R_*C_];
__device__ float g_t2    [R_*C_];
__device__ float g_ref   [R_*3];

// ---------------- reductions ----------------
__device__ __forceinline__ float warp_sum(float v){
#pragma unroll
    for (int o = 16; o; o >>= 1) v += __shfl_xor_sync(0xffffffffu, v, o);
    return v;
}
__device__ __forceinline__ float warp_max(float v){
#pragma unroll
    for (int o = 16; o; o >>= 1) v = fmaxf(v, __shfl_xor_sync(0xffffffffu, v, o));
    return v;
}

// ---------------- TF32 tensor-core GEMM ----------------
// C = epi(A (+A2) @ B + bias [+ Cres]), all fp32 in global, tf32 in MMA.
// BM=BN=128, BK=16. 256 threads = 8 warps in 2x4; warp tile 64x32 (4x2 wmma 16x16x8).
// EPI: 0=relu(.+b), 1=Cres+.+b, 2=.+b
template<bool ADD_A2, int EPI>
__global__ __launch_bounds__(256)
void tgemm(int M, int N, int K,
           const float* __restrict__ A, const float* __restrict__ A2,
           const float* __restrict__ Bm, const float* __restrict__ bias,
           const float* __restrict__ Cres, float* __restrict__ Cout)
{
    const int BM = 128, BN = 128, BK = 16;
    __shared__ float As[BM][BK + 4];     // tf32 bits, ldm = 20
    __shared__ float Bs[BK][BN + 4];     // tf32 bits, ldm = 132
    __shared__ float bias_s[16][BN];     // 16-row replicated bias tile

    const int tid = threadIdx.x;
    const int wid = tid >> 5;
    const int bm = blockIdx.y, bn = blockIdx.x;
    const int warp_m = wid >> 2;          // 0..1 -> 64 rows each
    const int warp_n = wid & 3;           // 0..3 -> 32 cols each

    // build replicated bias tile
    for (int idx = tid; idx < 16 * BN; idx += 256)
        bias_s[idx >> 7][idx & 127] = bias[bn * BN + (idx & 127)];
    __syncthreads();

    // init accumulators from bias
    wmma::fragment<wmma::accumulator, 16, 16, 8, float> acc[4][2];
    {
        wmma::fragment<wmma::accumulator, 16, 16, 8, float> bf[2];
#pragma unroll
        for (int j = 0; j < 2; j++)
            wmma::load_matrix_sync(bf[j], &bias_s[0][warp_n * 32 + j * 16], BN,
                                   wmma::mem_row_major);
#pragma unroll
        for (int i = 0; i < 4; i++)
#pragma unroll
            for (int j = 0; j < 2; j++)
#pragma unroll
                for (int e = 0; e < bf[j].num_elements; e++)
                    acc[i][j].x[e] = bf[j].x[e];
    }

    // global load indexing
    const int ar  = tid >> 2;             // 0..63, +64 for second row
    const int ac4 = (tid & 3) * 4;        // col group
    const int br  = tid >> 5;             // 0..7, +8 for second row
    const int bc4 = (tid & 31) * 4;

    const float* Ap  = A + (size_t)(bm * BM + ar) * K + ac4;
    const float* A2p = ADD_A2 ? (A2 + (size_t)(bm * BM + ar) * K + ac4) : nullptr;
    const float* Bp  = Bm + (size_t)br * N + bn * BN + bc4;

    for (int k0 = 0; k0 < K; k0 += BK) {
        // A tile: 128 x 16 (two 64-row halves per thread)
#pragma unroll
        for (int h = 0; h < 2; h++) {
            float4 av = *(const float4*)(Ap + (size_t)h * 64 * K);
            if (ADD_A2) {
                float4 a2 = *(const float4*)(A2p + (size_t)h * 64 * K);
                av.x += a2.x; av.y += a2.y; av.z += a2.z; av.w += a2.w;
            }
            int r = ar + h * 64;
            As[r][ac4 + 0] = wmma::__float_to_tf32(av.x);
            As[r][ac4 + 1] = wmma::__float_to_tf32(av.y);
            As[r][ac4 + 2] = wmma::__float_to_tf32(av.z);
            As[r][ac4 + 3] = wmma::__float_to_tf32(av.w);
        }
        // B tile: 16 x 128 (two 8-row halves per thread)
#pragma unroll
        for (int h = 0; h < 2; h++) {
            float4 bv = *(const float4*)(Bp + (size_t)h * 8 * N);
            int r = br + h * 8;
            Bs[r][bc4 + 0] = wmma::__float_to_tf32(bv.x);
            Bs[r][bc4 + 1] = wmma::__float_to_tf32(bv.y);
            Bs[r][bc4 + 2] = wmma::__float_to_tf32(bv.z);
            Bs[r][bc4 + 3] = wmma::__float_to_tf32(bv.w);
        }
        __syncthreads();
        Ap += BK;
        if (ADD_A2) A2p += BK;
        Bp += (size_t)BK * N;

#pragma unroll
        for (int kk = 0; kk < BK; kk += 8) {
            wmma::fragment<wmma::matrix_a, 16, 16, 8, wmma::precision::tf32, wmma::row_major> af[4];
            wmma::fragment<wmma::matrix_b, 16, 16, 8, wmma::precision::tf32, wmma::row_major> bfr[2];
#pragma unroll
            for (int i = 0; i < 4; i++)
                wmma::load_matrix_sync(af[i], &As[warp_m * 64 + i * 16][kk], BK + 4);
#pragma unroll
            for (int j = 0; j < 2; j++)
                wmma::load_matrix_sync(bfr[j], &Bs[kk][warp_n * 32 + j * 16], BN + 4);
#pragma unroll
            for (int i = 0; i < 4; i++)
#pragma unroll
                for (int j = 0; j < 2; j++)
                    wmma::mma_sync(acc[i][j], af[i], bfr[j], acc[i][j]);
        }
        __syncthreads();
    }

    // epilogue
#pragma unroll
    for (int i = 0; i < 4; i++) {
        int row = bm * BM + warp_m * 64 + i * 16;
#pragma unroll
        for (int j = 0; j < 2; j++) {
            int col = bn * BN + warp_n * 32 + j * 16;
            if (EPI == 0) {
#pragma unroll
                for (int e = 0; e < acc[i][j].num_elements; e++)
                    acc[i][j].x[e] = fmaxf(acc[i][j].x[e], 0.f);
            } else if (EPI == 1) {
                wmma::fragment<wmma::accumulator, 16, 16, 8, float> cf;
                wmma::load_matrix_sync(cf, Cres + (size_t)row * N + col, N,
                                       wmma::mem_row_major);
#pragma unroll
                for (int e = 0; e < cf.num_elements; e++)
                    acc[i][j].x[e] += cf.x[e];
            }
            wmma::store_matrix_sync(Cout + (size_t)row * N + col, acc[i][j], N,
                                    wmma::mem_row_major);
        }
    }
}

// ---------------- logits init: log(max(p,1e-8)) ----------------
__global__ void logits_init(const float* __restrict__ p, float* __restrict__ lg)
{
    int i = blockIdx.x * blockDim.x + threadIdx.x;
    if (i < R_*P_) lg[i] = logf(fmaxf(p[i], 1e-8f));
}

// ---------------- plain row LN (256 cols, 128 threads) ----------------
__global__ void ln_rows(const float* __restrict__ in, float* __restrict__ out)
{
    int row = blockIdx.x, t = threadIdx.x;
    int w = t >> 5, lane = t & 31;
    __shared__ float sr[8];
    float x0 = in[(size_t)row*C_ + t];
    float x1 = in[(size_t)row*C_ + 128 + t];
    float s1 = warp_sum(x0 + x1);
    float s2 = warp_sum(x0*x0 + x1*x1);
    if (lane == 0) { sr[w] = s1; sr[4+w] = s2; }
    __syncthreads();
    float m  = (sr[0]+sr[1]+sr[2]+sr[3]) * (1.f/256.f);
    float vv = (sr[4]+sr[5]+sr[6]+sr[7]) * (1.f/256.f) - m*m;
    float r  = rsqrtf(vv + 1e-5f);
    out[(size_t)row*C_ + t]       = (x0 - m) * r;
    out[(size_t)row*C_ + 128 + t] = (x1 - m) * r;
}

// ---------------- per-row fused: LN->interm, logits+softmax, ref einsum ----------------
__global__ void row_kernel(int layer,
                           const float* __restrict__ query,
                           const float* __restrict__ S,
                           const float* __restrict__ coords,
                           const int* __restrict__ mask,
                           const float* __restrict__ pn_scale,
                           const float* __restrict__ pn_bias,
                           float* __restrict__ logits_st,
                           float* __restrict__ probs,
                           float* __restrict__ ref_st,
                           float* __restrict__ out)
{
    int row = blockIdx.x, t = threadIdx.x;
    int w = t >> 5, lane = t & 31;
    __shared__ float sr[12];

    // --- layernorm of query -> interm output ---
    float x0 = query[(size_t)row*C_ + t];
    float x1 = query[(size_t)row*C_ + 128 + t];
    float s1 = warp_sum(x0 + x1);
    float s2 = warp_sum(x0*x0 + x1*x1);
    if (lane == 0) { sr[w] = s1; sr[4+w] = s2; }
    __syncthreads();
    float m    = (sr[0]+sr[1]+sr[2]+sr[3]) * (1.f/256.f);
    float var  = (sr[4]+sr[5]+sr[6]+sr[7]) * (1.f/256.f) - m*m;
    float rstd = rsqrtf(var + 1e-5f);
    size_t ib = INTERM_OFF + (size_t)layer*R_*C_ + (size_t)row*C_;
    out[ib + t]       = (x0 - m)*rstd*pn_scale[t]       + pn_bias[t];
    out[ib + 128 + t] = (x1 - m)*rstd*pn_scale[128 + t] + pn_bias[128 + t];

    // --- masked logits residual update ---
    float mf = mask[row] ? 1.f : 0.f;
    size_t li = (size_t)row*P_ + t;
    float lg = logits_st[li] + S[li] * mf;
    logits_st[li] = lg;
    out[LOGITS_OFF + (size_t)layer*R_*P_ + li] = lg;

    // --- softmax over 128 ---
    float mx = warp_max(lg);
    __syncthreads();
    if (lane == 0) sr[w] = mx;
    __syncthreads();
    mx = fmaxf(fmaxf(sr[0], sr[1]), fmaxf(sr[2], sr[3]));
    float e = __expf(lg - mx);
    float se = warp_sum(e);
    __syncthreads();
    if (lane == 0) sr[w] = se;
    __syncthreads();
    se = sr[0]+sr[1]+sr[2]+sr[3];
    float p = e / se;
    probs[li] = p;

    // --- dyn_ref = probs @ coords[row] (128x3) ---
    const float* cr = coords + (size_t)row*P_*3 + (size_t)t*3;
    float r0 = warp_sum(p * cr[0]);
    float r1 = warp_sum(p * cr[1]);
    float r2 = warp_sum(p * cr[2]);
    __syncthreads();
    if (lane == 0) { sr[w] = r0; sr[4+w] = r1; sr[8+w] = r2; }
    __syncthreads();
    if (t == 0) {
        float d0 = sr[0]+sr[1]+sr[2]+sr[3];
        float d1 = sr[4]+sr[5]+sr[6]+sr[7];
        float d2 = sr[8]+sr[9]+sr[10]+sr[11];
        float o0, o1, o2;
        if (mf > 0.f) { o0 = d0; o1 = d1; o2 = d2; }
        else { o0 = ref_st[row*3]; o1 = ref_st[row*3+1]; o2 = ref_st[row*3+2]; }
        ref_st[row*3] = o0; ref_st[row*3+1] = o1; ref_st[row*3+2] = o2;
        size_t rb = REFS_OFF + (size_t)(layer+1)*R_*3 + (size_t)row*3;
        out[rb] = o0; out[rb+1] = o1; out[rb+2] = o2;
    }
}

// ---------------- masked query_pos update ----------------
__global__ void pos_update(const float* __restrict__ t1, const float* __restrict__ t2,
                           const float* __restrict__ lnp, const int* __restrict__ mask,
                           float* __restrict__ qpos)
{
    int idx = blockIdx.x * blockDim.x + threadIdx.x;
    if (idx >= R_*C_) return;
    int row = idx >> 8;
    if (mask[row]) qpos[idx] = lnp[idx] * t1[idx] + t2[idx];
}

// ---------------- host ----------------
extern "C" void kernel_launch(void* const* d_in, const int* in_sizes, int n_in,
                              void* d_out, int out_size)
{
    const float*   query      = (const float*)d_in[0];
    const float*   query_pos  = (const float*)d_in[1];
    const float*   refpts     = (const float*)d_in[2];
    const float*   coords     = (const float*)d_in[3];
    const float*   dprobs     = (const float*)d_in[4];
    const int*     mask       = (const int*)d_in[5];
    const float*   layer_w1   = (const float*)d_in[6];
    const float*   layer_b1   = (const float*)d_in[7];
    const float*   layer_w2   = (const float*)d_in[8];
    const float*   layer_b2   = (const float*)d_in[9];
    const float*   prob_w     = (const float*)d_in[10];
    const float*   prob_b     = (const float*)d_in[11];
    const float*   pos_w      = (const float*)d_in[12];
    const float*   pos_b      = (const float*)d_in[13];
    const float*   g_w        = (const float*)d_in[14];
    const float*   g_b        = (const float*)d_in[15];
    const float*   be_w       = (const float*)d_in[16];
    const float*   be_b       = (const float*)d_in[17];
    const float*   pn_scale   = (const float*)d_in[18];
    const float*   pn_bias    = (const float*)d_in[19];
    float* out = (float*)d_out;

    float *q, *qp, *H, *lg, *S, *pb, *lnp, *t1, *t2, *ref;
    cudaGetSymbolAddress((void**)&q,   g_query);
    cudaGetSymbolAddress((void**)&qp,  g_qpos);
    cudaGetSymbolAddress((void**)&H,   g_H);
    cudaGetSymbolAddress((void**)&lg,  g_logits);
    cudaGetSymbolAddress((void**)&S,   g_S);
    cudaGetSymbolAddress((void**)&pb,  g_probs);
    cudaGetSymbolAddress((void**)&lnp, g_lnpos);
    cudaGetSymbolAddress((void**)&t1,  g_t1);
    cudaGetSymbolAddress((void**)&t2,  g_t2);
    cudaGetSymbolAddress((void**)&ref, g_ref);

    // init state
    cudaMemcpyAsync(q,   query,     (size_t)R_*C_*4, cudaMemcpyDeviceToDevice);
    cudaMemcpyAsync(qp,  query_pos, (size_t)R_*C_*4, cudaMemcpyDeviceToDevice);
    cudaMemcpyAsync(ref, refpts,    (size_t)R_*3*4,  cudaMemcpyDeviceToDevice);
    cudaMemcpyAsync(out + REFS_OFF, refpts, (size_t)R_*3*4, cudaMemcpyDeviceToDevice);

    logits_init<<<(R_*P_ + 255)/256, 256>>>(dprobs, lg);

    // pos_base = coords.reshape(R,384) @ pos_w + pos_b ; then LN -> g_lnpos
    tgemm<false,2><<<dim3(C_/128, R_/128), 256>>>(R_, C_, P_*3, coords, nullptr,
                                                  pos_w, pos_b, nullptr, t1);
    ln_rows<<<R_, 128>>>(t1, lnp);

    for (int i = 0; i < L_; i++) {
        // H = relu((q+qp) @ W1 + b1)
        tgemm<true,0><<<dim3(FF_/128, R_/128), 256>>>(R_, FF_, C_,
            q, qp, layer_w1 + (size_t)i*C_*FF_, layer_b1 + (size_t)i*FF_, nullptr, H);
        // q = q + H @ W2 + b2
        tgemm<false,1><<<dim3(C_/128, R_/128), 256>>>(R_, C_, FF_,
            H, nullptr, layer_w2 + (size_t)i*FF_*C_, layer_b2 + (size_t)i*C_, q, q);
        // S = q @ prob_w + prob_b
        tgemm<false,2><<<dim3(P_/128, R_/128), 256>>>(R_, P_, C_,
            q, nullptr, prob_w + (size_t)i*C_*P_, prob_b + (size_t)i*P_, nullptr, S);
        // per-row fused ops
        row_kernel<<<R_, 128>>>(i, q, S, coords, mask, pn_scale, pn_bias,
                                lg, pb, ref, out);
        // t1 = probs @ g_w + g_b ; t2 = probs @ be_w + be_b
        tgemm<false,2><<<dim3(C_/128, R_/128), 256>>>(R_, C_, P_,
            pb, nullptr, g_w, g_b, nullptr, t1);
        tgemm<false,2><<<dim3(C_/128, R_/128), 256>>>(R_, C_, P_,
            pb, nullptr, be_w, be_b, nullptr, t2);
        // qpos = mask ? lnpos * t1 + t2 : qpos
        pos_update<<<(R_*C_ + 255)/256, 256>>>(t1, t2, lnp, mask, qp);
    }
    (void)in_sizes; (void)n_in; (void)out_size;
}